// round 15
// baseline (speedup 1.0000x reference)
#include <cuda_runtime.h>
#include <cuda_fp16.h>
#include <math.h>

#define BATCH 32
#define LSEQ  1024
#define DIM   128

#define BM 64            // Q rows per CTA (4 warps x 16 rows)
#define BN 32            // K/V rows per tile
#define NTILES (LSEQ / BN)
#define NSPLIT 4
#define TILES_PER_SPLIT (NTILES / NSPLIT)   // 8
#define NTH 128

// u32 strides (fp16 pairs per row + pad) -> conflict-free ldmatrix
#define QS2 68
#define KS2 68
#define VS2 68

// smem offsets in u32 units: Q | K0 V0 | K1 V1
#define OFF_Q  0
#define OFF_B  (OFF_Q + BM * QS2)          // 4352
#define BUFSZ  (2 * BN * KS2)              // 4352 (K tile + V tile)
#define SMEM_U32 (OFF_B + 2 * BUFSZ)       // 13056
#define SMEM_BYTES (SMEM_U32 * 4)          // 52224 B -> 4 CTAs/SM

// fp16 scratch for K and V + split-KV partial accumulators
#define SCRATCH_U32 (BATCH * LSEQ * DIM / 2)
__device__ unsigned gK16[SCRATCH_U32];
__device__ unsigned gV16[SCRATCH_U32];
__device__ float gOacc[NSPLIT * BATCH * LSEQ * DIM];   // 64 MB
__device__ float gLacc[NSPLIT * BATCH * LSEQ];

__device__ __forceinline__ unsigned f16pack(float x0, float x1) {
    unsigned r; asm("cvt.rn.f16x2.f32 %0, %1, %2;" : "=r"(r) : "f"(x1), "f"(x0));
    return r;
}
__device__ __forceinline__ float ex2f(float x) {
    float r; asm("ex2.approx.f32 %0, %1;" : "=f"(r) : "f"(x)); return r;
}
__device__ __forceinline__ void mma_f16(float* c,
                                        unsigned a0, unsigned a1, unsigned a2, unsigned a3,
                                        unsigned b0, unsigned b1) {
    asm volatile(
        "mma.sync.aligned.m16n8k16.row.col.f32.f16.f16.f32 "
        "{%0,%1,%2,%3},{%4,%5,%6,%7},{%8,%9},{%0,%1,%2,%3};"
        : "+f"(c[0]), "+f"(c[1]), "+f"(c[2]), "+f"(c[3])
        : "r"(a0), "r"(a1), "r"(a2), "r"(a3), "r"(b0), "r"(b1));
}
__device__ __forceinline__ void ldsm4(unsigned& r0, unsigned& r1, unsigned& r2,
                                      unsigned& r3, unsigned addr) {
    asm volatile("ldmatrix.sync.aligned.m8n8.x4.shared.b16 {%0,%1,%2,%3}, [%4];"
                 : "=r"(r0), "=r"(r1), "=r"(r2), "=r"(r3) : "r"(addr));
}
__device__ __forceinline__ void ldsm4t(unsigned& r0, unsigned& r1, unsigned& r2,
                                       unsigned& r3, unsigned addr) {
    asm volatile("ldmatrix.sync.aligned.m8n8.x4.trans.shared.b16 {%0,%1,%2,%3}, [%4];"
                 : "=r"(r0), "=r"(r1), "=r"(r2), "=r"(r3) : "r"(addr));
}
__device__ __forceinline__ unsigned smem_u32(const void* p) {
    unsigned a;
    asm("{ .reg .u64 t; cvta.to.shared.u64 t, %1; cvt.u32.u64 %0, t; }" : "=r"(a) : "l"(p));
    return a;
}
__device__ __forceinline__ void cp16(unsigned dst, const void* src) {
    asm volatile("cp.async.cg.shared.global [%0], [%1], 16;" :: "r"(dst), "l"(src) : "memory");
}
#define CP_COMMIT() asm volatile("cp.async.commit_group;" ::: "memory")
#define CP_WAIT0()  asm volatile("cp.async.wait_group 0;" ::: "memory")

__device__ __forceinline__ int read_vl(const void* vlenp, int i) {
    const int* pi = (const int*)vlenp;
    bool is64 = true;
    #pragma unroll
    for (int j = 0; j < 16; j++) is64 &= (pi[2 * j + 1] == 0);
    return is64 ? (int)((const long long*)vlenp)[i] : pi[i];
}
__device__ __forceinline__ int eff_tiles(int vl) {
    return (vl == 0) ? NTILES : (vl + BN - 1) / BN;
}

// ---- convert pre-pass: f32 K,V -> fp16 scratch, only rows that will be read ----
__global__ __launch_bounds__(256)
void cvt_kv_kernel(const float* __restrict__ K, const float* __restrict__ V,
                   const void* __restrict__ vlenp)
{
    int idx = blockIdx.x * 256 + threadIdx.x;   // float4 index
    int b = idx >> 15;
    int token = (idx & 32767) >> 5;
    if (token >= eff_tiles(read_vl(vlenp, b)) * BN) return;
    float4 k = ((const float4*)K)[idx];
    uint2 a;
    a.x = f16pack(k.x, k.y);
    a.y = f16pack(k.z, k.w);
    ((uint2*)gK16)[idx] = a;
    float4 v = ((const float4*)V)[idx];
    uint2 c;
    c.x = f16pack(v.x, v.y);
    c.y = f16pack(v.z, v.w);
    ((uint2*)gV16)[idx] = c;
}

// ---- normalize: out = sum_c O_c / sum_c l_c over active splits ----
__global__ __launch_bounds__(256)
void norm_kernel(const void* __restrict__ vlenp, float* __restrict__ Og)
{
    int idx = blockIdx.x * 256 + threadIdx.x;   // float4 index over [32][1024][32]
    int b = idx >> 15;
    int row = (idx & 32767) >> 5;
    int S = (eff_tiles(read_vl(vlenp, b)) + TILES_PER_SPLIT - 1) / TILES_PER_SPLIT;
    float4 acc = make_float4(0.f, 0.f, 0.f, 0.f);
    float l = 0.f;
    for (int c = 0; c < S; c++) {
        const float4* src = (const float4*)gOacc + (size_t)c * (BATCH * LSEQ * 32) + idx;
        float4 v = *src;
        acc.x += v.x; acc.y += v.y; acc.z += v.z; acc.w += v.w;
        l += gLacc[(size_t)c * (BATCH * LSEQ) + b * LSEQ + row];
    }
    float inv = 1.0f / l;
    acc.x *= inv; acc.y *= inv; acc.z *= inv; acc.w *= inv;
    ((float4*)Og)[idx] = acc;
}

// prefetch one K/V fp16 tile (8 KB each) into smem buffer via cp.async
__device__ __forceinline__ void prefetch_tile(unsigned dstK, unsigned dstV,
                                              const char* srcK, const char* srcV, int t)
{
    #pragma unroll
    for (int i = 0; i < 4; i++) {
        int idx = i * NTH + t;               // 16B chunk id, 512 per tile
        int r = idx >> 4, c = idx & 15;
        cp16(dstK + r * (KS2 * 4) + c * 16, srcK + r * 256 + c * 16);
        cp16(dstV + r * (VS2 * 4) + c * 16, srcV + r * 256 + c * 16);
    }
    CP_COMMIT();
}

__global__ __launch_bounds__(NTH, 4)
void fa_f16_split_kernel(const float* __restrict__ Qg,
                         const void*  __restrict__ vlenp)
{
    extern __shared__ unsigned smem[];
    unsigned* Qs = smem + OFF_Q;
    const unsigned su = smem_u32(smem);

    const int b  = blockIdx.y;
    const int qb = blockIdx.x * BM;
    const int sp = blockIdx.z;              // KV split 0..3
    const int t  = threadIdx.x;
    const int w  = t >> 5;
    const int lane = t & 31;
    const int q4 = lane & 3;
    const int g8 = lane >> 2;
    const int l7  = lane & 7;
    const int l8  = (lane >> 3) & 1;
    const int l16 = lane >> 4;

    const int vl = read_vl(vlenp, b);
    const float mk = (vl == 0) ? 1.0f : 0.0f;
    const int ntiles = eff_tiles(vl);

    const int t0 = sp * TILES_PER_SPLIT;
    const int t1 = min(t0 + TILES_PER_SPLIT, ntiles);
    if (t0 >= t1) return;                   // inactive split: no work, no writes

    // fp16 scratch row = 256 bytes
    const char* kbase = (const char*)gK16 + (size_t)b * LSEQ * 256;
    const char* vbase = (const char*)gV16 + (size_t)b * LSEQ * 256;

    // ---- prefetch first tile of this split into buffer 0 ----
    prefetch_tile(su + 4 * OFF_B, su + 4 * (OFF_B + BN * KS2),
                  kbase + (size_t)t0 * BN * 256, vbase + (size_t)t0 * BN * 256, t);

    // ---- load Q tile (f32 LDG, scaled; overlaps cp.async) ----
    {
        const float scale = 0.12752867359570686f;   // log2(e)/sqrt(128)
        const float* qsrc = Qg + ((size_t)b * LSEQ + qb) * DIM;
        #pragma unroll
        for (int i = 0; i < 16; i++) {
            int idx = i * NTH + t;
            int r = idx >> 5, c = (idx & 31) * 4;
            float4 v = *(const float4*)(qsrc + r * DIM + c);
            uint2 h;
            h.x = f16pack(v.x * scale, v.y * scale);
            h.y = f16pack(v.z * scale, v.w * scale);
            *(uint2*)&Qs[r * QS2 + (c >> 1)] = h;
        }
    }

    CP_WAIT0();
    __syncthreads();

    float l_l = 0.f, l_h = 0.f;
    float o[16][4];
    #pragma unroll
    for (int n = 0; n < 16; n++)
        #pragma unroll
        for (int i = 0; i < 4; i++) o[n][i] = 0.f;

    // ---- ldmatrix base addresses (bytes) ----
    const unsigned qAddr0 = su + 4u * (OFF_Q + (16 * w + l7 + 8 * l8) * QS2 + 4 * l16);
    const unsigned kOff = 4u * ((8 * l16 + l7) * KS2 + 4 * l8);
    const unsigned vOff = 4u * ((8 * l8 + l7) * VS2 + 4 * l16);

    for (int kt = t0; kt < t1; kt++) {
        const int p = (kt - t0) & 1;
        const unsigned bufK = su + 4u * (OFF_B + p * BUFSZ);
        const unsigned bufV = bufK + 4u * (BN * KS2);

        // ---- prefetch tile kt+1 into the other buffer ----
        if (kt + 1 < t1) {
            unsigned nK = su + 4u * (OFF_B + (p ^ 1) * BUFSZ);
            prefetch_tile(nK, nK + 4u * (BN * KS2),
                          kbase + (size_t)(kt + 1) * BN * 256,
                          vbase + (size_t)(kt + 1) * BN * 256, t);
        }

        // ---- S = Q @ K^T : single fp16 pass ----
        float sc[4][4];
        #pragma unroll
        for (int j = 0; j < 4; j++)
            #pragma unroll
            for (int i = 0; i < 4; i++) sc[j][i] = 0.f;

        const unsigned kAddr0 = bufK + kOff;
        #pragma unroll
        for (int kc = 0; kc < 8; kc++) {
            unsigned a0, a1, a2, a3;
            ldsm4(a0, a1, a2, a3, qAddr0 + kc * 32);
            unsigned b0[4], b1[4];
            ldsm4(b0[0], b0[1], b0[2], b0[3], kAddr0 + kc * 32);
            ldsm4(b1[0], b1[1], b1[2], b1[3], kAddr0 + 16 * KS2 * 4 + kc * 32);
            mma_f16(sc[0], a0, a1, a2, a3, b0[0], b0[1]);
            mma_f16(sc[1], a0, a1, a2, a3, b0[2], b0[3]);
            mma_f16(sc[2], a0, a1, a2, a3, b1[0], b1[1]);
            mma_f16(sc[3], a0, a1, a2, a3, b1[2], b1[3]);
        }

        // ---- softmax numerator: p = 2^s, masked -> mk ----
        const int rel = vl - kt * BN;
        #pragma unroll
        for (int j = 0; j < 4; j++) {
            int c0 = 8 * j + 2 * q4;
            float p0 = ex2f(sc[j][0]);
            float p1 = ex2f(sc[j][1]);
            float p2 = ex2f(sc[j][2]);
            float p3 = ex2f(sc[j][3]);
            p0 = (c0     < rel) ? p0 : mk;
            p1 = (c0 + 1 < rel) ? p1 : mk;
            p2 = (c0     < rel) ? p2 : mk;
            p3 = (c0 + 1 < rel) ? p3 : mk;
            sc[j][0] = p0; sc[j][1] = p1; sc[j][2] = p2; sc[j][3] = p3;
            l_l += p0 + p1;
            l_h += p2 + p3;
        }

        // ---- O += P @ V : single fp16 pass, trans-ldmatrix B frags ----
        const unsigned vAddr0 = bufV + vOff;
        #pragma unroll
        for (int jj = 0; jj < 2; jj++) {
            unsigned a0 = f16pack(sc[2*jj][0],   sc[2*jj][1]);
            unsigned a1 = f16pack(sc[2*jj][2],   sc[2*jj][3]);
            unsigned a2 = f16pack(sc[2*jj+1][0], sc[2*jj+1][1]);
            unsigned a3 = f16pack(sc[2*jj+1][2], sc[2*jj+1][3]);
            unsigned vA = vAddr0 + jj * 16 * VS2 * 4;
            #pragma unroll
            for (int m = 0; m < 8; m++) {
                unsigned h0, h1, h2, h3;
                ldsm4t(h0, h1, h2, h3, vA + m * 32);
                mma_f16(o[2 * m],     a0, a1, a2, a3, h0, h1);
                mma_f16(o[2 * m + 1], a0, a1, a2, a3, h2, h3);
            }
        }

        // ---- rotate buffers ----
        if (kt + 1 < t1) {
            CP_WAIT0();
            __syncthreads();
        }
    }

    // ---- epilogue: write raw partials (no normalization) ----
    l_l += __shfl_xor_sync(0xffffffffu, l_l, 1);
    l_l += __shfl_xor_sync(0xffffffffu, l_l, 2);
    l_h += __shfl_xor_sync(0xffffffffu, l_h, 1);
    l_h += __shfl_xor_sync(0xffffffffu, l_h, 2);

    const int row_l = qb + 16 * w + g8;
    float* obase = gOacc + ((size_t)sp * BATCH + b) * LSEQ * DIM;
    #pragma unroll
    for (int n = 0; n < 16; n++) {
        int col = 8 * n + 2 * q4;
        *(float2*)&obase[(size_t)row_l * DIM + col]       = make_float2(o[n][0], o[n][1]);
        *(float2*)&obase[(size_t)(row_l + 8) * DIM + col] = make_float2(o[n][2], o[n][3]);
    }
    if (q4 == 0) {
        float* lb = gLacc + ((size_t)sp * BATCH + b) * LSEQ;
        lb[row_l]     = l_l;
        lb[row_l + 8] = l_h;
    }
}

extern "C" void kernel_launch(void* const* d_in, const int* in_sizes, int n_in,
                              void* d_out, int out_size)
{
    const float* Q = (const float*)d_in[0];
    const float* K = (const float*)d_in[1];
    const float* V = (const float*)d_in[2];
    const void*  vlen = d_in[3];
    float* O = (float*)d_out;

    // pre-pass: convert only the K/V rows that will be read
    int n4 = BATCH * LSEQ * DIM / 4;
    cvt_kv_kernel<<<n4 / 256, 256>>>(K, V, vlen);

    cudaFuncSetAttribute(fa_f16_split_kernel,
                         cudaFuncAttributeMaxDynamicSharedMemorySize, SMEM_BYTES);
    dim3 grid(LSEQ / BM, BATCH, NSPLIT);
    fa_f16_split_kernel<<<grid, NTH, SMEM_BYTES>>>(Q, vlen);

    // combine partials and normalize
    norm_kernel<<<n4 / 256, 256>>>(vlen, O);
}

// round 16
// speedup vs baseline: 1.3654x; 1.3654x over previous
#include <cuda_runtime.h>
#include <cuda_fp16.h>
#include <math.h>

#define BATCH 32
#define LSEQ  1024
#define DIM   128

#define BM 64            // Q rows per CTA (4 warps x 16 rows)
#define BN 32            // K/V rows per tile
#define NTILES (LSEQ / BN)
#define NTH 128
#define NSTAGE 3

// u32 strides (fp16 pairs per row + pad) -> conflict-free ldmatrix
#define QS2 68
#define KS2 68
#define VS2 68

// smem offsets in u32 units: Q | stage0 | stage1 | stage2
#define OFF_Q  0
#define OFF_B  (OFF_Q + BM * QS2)          // 4352
#define BUFSZ  (2 * BN * KS2)              // 4352 u32 (K tile + V tile)
#define SMEM_U32 (OFF_B + NSTAGE * BUFSZ)  // 17408
#define SMEM_BYTES (SMEM_U32 * 4)          // 69632 B -> 3 CTAs/SM (208.9KB)

// fp16 scratch for K and V (converted once by pre-pass kernel)
#define SCRATCH_U32 (BATCH * LSEQ * DIM / 2)
__device__ unsigned gK16[SCRATCH_U32];
__device__ unsigned gV16[SCRATCH_U32];

__device__ __forceinline__ unsigned f16pack(float x0, float x1) {
    unsigned r; asm("cvt.rn.f16x2.f32 %0, %1, %2;" : "=r"(r) : "f"(x1), "f"(x0));
    return r;
}
__device__ __forceinline__ float ex2f(float x) {
    float r; asm("ex2.approx.f32 %0, %1;" : "=f"(r) : "f"(x)); return r;
}
__device__ __forceinline__ void mma_f16(float* c,
                                        unsigned a0, unsigned a1, unsigned a2, unsigned a3,
                                        unsigned b0, unsigned b1) {
    asm volatile(
        "mma.sync.aligned.m16n8k16.row.col.f32.f16.f16.f32 "
        "{%0,%1,%2,%3},{%4,%5,%6,%7},{%8,%9},{%0,%1,%2,%3};"
        : "+f"(c[0]), "+f"(c[1]), "+f"(c[2]), "+f"(c[3])
        : "r"(a0), "r"(a1), "r"(a2), "r"(a3), "r"(b0), "r"(b1));
}
__device__ __forceinline__ void ldsm4(unsigned& r0, unsigned& r1, unsigned& r2,
                                      unsigned& r3, unsigned addr) {
    asm volatile("ldmatrix.sync.aligned.m8n8.x4.shared.b16 {%0,%1,%2,%3}, [%4];"
                 : "=r"(r0), "=r"(r1), "=r"(r2), "=r"(r3) : "r"(addr));
}
__device__ __forceinline__ void ldsm4t(unsigned& r0, unsigned& r1, unsigned& r2,
                                       unsigned& r3, unsigned addr) {
    asm volatile("ldmatrix.sync.aligned.m8n8.x4.trans.shared.b16 {%0,%1,%2,%3}, [%4];"
                 : "=r"(r0), "=r"(r1), "=r"(r2), "=r"(r3) : "r"(addr));
}
__device__ __forceinline__ unsigned smem_u32(const void* p) {
    unsigned a;
    asm("{ .reg .u64 t; cvta.to.shared.u64 t, %1; cvt.u32.u64 %0, t; }" : "=r"(a) : "l"(p));
    return a;
}
__device__ __forceinline__ void cp16(unsigned dst, const void* src) {
    asm volatile("cp.async.cg.shared.global [%0], [%1], 16;" :: "r"(dst), "l"(src) : "memory");
}
#define CP_COMMIT() asm volatile("cp.async.commit_group;" ::: "memory")
#define CP_WAIT0()  asm volatile("cp.async.wait_group 0;" ::: "memory")
#define CP_WAIT1()  asm volatile("cp.async.wait_group 1;" ::: "memory")

__device__ __forceinline__ int read_vl(const void* vlenp, int i) {
    const int* pi = (const int*)vlenp;
    bool is64 = true;
    #pragma unroll
    for (int j = 0; j < 16; j++) is64 &= (pi[2 * j + 1] == 0);
    return is64 ? (int)((const long long*)vlenp)[i] : pi[i];
}

// ---- convert pre-pass: f32 K,V -> fp16 scratch, only rows that will be read ----
__global__ __launch_bounds__(256)
void cvt_kv_kernel(const float* __restrict__ K, const float* __restrict__ V,
                   const void* __restrict__ vlenp)
{
    int idx = blockIdx.x * 256 + threadIdx.x;   // float4 index
    int b = idx >> 15;
    int token = (idx & 32767) >> 5;
    int vl = read_vl(vlenp, b);
    int eff = (vl == 0) ? LSEQ : vl;
    if (token >= ((eff + BN - 1) / BN) * BN) return;
    float4 k = ((const float4*)K)[idx];
    uint2 a;
    a.x = f16pack(k.x, k.y);
    a.y = f16pack(k.z, k.w);
    ((uint2*)gK16)[idx] = a;
    float4 v = ((const float4*)V)[idx];
    uint2 c;
    c.x = f16pack(v.x, v.y);
    c.y = f16pack(v.z, v.w);
    ((uint2*)gV16)[idx] = c;
}

// prefetch one K/V fp16 tile (8 KB each) into a smem stage via cp.async
__device__ __forceinline__ void prefetch_tile(unsigned dstK, unsigned dstV,
                                              const char* srcK, const char* srcV, int t)
{
    #pragma unroll
    for (int i = 0; i < 4; i++) {
        int idx = i * NTH + t;               // 16B chunk id, 512 per tile
        int r = idx >> 4, c = idx & 15;
        cp16(dstK + r * (KS2 * 4) + c * 16, srcK + r * 256 + c * 16);
        cp16(dstV + r * (VS2 * 4) + c * 16, srcV + r * 256 + c * 16);
    }
    CP_COMMIT();
}

__global__ __launch_bounds__(NTH, 3)
void fa_f16_ring_kernel(const float* __restrict__ Qg,
                        const void*  __restrict__ vlenp,
                        float* __restrict__ Og)
{
    extern __shared__ unsigned smem[];
    unsigned* Qs = smem + OFF_Q;
    const unsigned su = smem_u32(smem);

    const int t  = threadIdx.x;
    const int w  = t >> 5;
    const int lane = t & 31;
    const int q4 = lane & 3;
    const int g8 = lane >> 2;
    const int l7  = lane & 7;
    const int l8  = (lane >> 3) & 1;
    const int l16 = lane >> 4;

    // ---- inline LPT: rank all 32 batches, pick the one with rank == blockIdx.y ----
    int b, vl;
    {
        int my_vl  = read_vl(vlenp, lane);
        int my_eff = (my_vl == 0) ? LSEQ : my_vl;
        int rank = 0;
        #pragma unroll
        for (int j = 0; j < BATCH; j++) {
            int effj = __shfl_sync(0xffffffffu, my_eff, j);
            rank += (effj > my_eff) || (effj == my_eff && j < lane);
        }
        unsigned m = __ballot_sync(0xffffffffu, rank == (int)blockIdx.y);
        b = __ffs(m) - 1;
        vl = __shfl_sync(0xffffffffu, my_vl, b);
    }
    const int qb = blockIdx.x * BM;
    const float mk = (vl == 0) ? 1.0f : 0.0f;
    const int ntiles = (vl == 0) ? NTILES : (vl + BN - 1) / BN;

    // fp16 scratch row = 256 bytes
    const char* kbase = (const char*)gK16 + (size_t)b * LSEQ * 256;
    const char* vbase = (const char*)gV16 + (size_t)b * LSEQ * 256;

    // ---- preamble: prefetch tiles 0 and 1 into stages 0,1 ----
    prefetch_tile(su + 4 * OFF_B, su + 4 * (OFF_B + BN * KS2), kbase, vbase, t);
    if (1 < ntiles) {
        unsigned s1 = su + 4u * (OFF_B + BUFSZ);
        prefetch_tile(s1, s1 + 4u * (BN * KS2),
                      kbase + (size_t)BN * 256, vbase + (size_t)BN * 256, t);
    }

    // ---- load Q tile (f32 LDG, scaled; overlaps cp.async) ----
    {
        const float scale = 0.12752867359570686f;   // log2(e)/sqrt(128)
        const float* qsrc = Qg + ((size_t)b * LSEQ + qb) * DIM;
        #pragma unroll
        for (int i = 0; i < 16; i++) {
            int idx = i * NTH + t;
            int r = idx >> 5, c = (idx & 31) * 4;
            float4 v = *(const float4*)(qsrc + r * DIM + c);
            uint2 h;
            h.x = f16pack(v.x * scale, v.y * scale);
            h.y = f16pack(v.z * scale, v.w * scale);
            *(uint2*)&Qs[r * QS2 + (c >> 1)] = h;
        }
    }

    if (1 < ntiles) { CP_WAIT1(); } else { CP_WAIT0(); }   // tile-0 group done
    __syncthreads();

    float l_l = 0.f, l_h = 0.f;
    float o[16][4];
    #pragma unroll
    for (int n = 0; n < 16; n++)
        #pragma unroll
        for (int i = 0; i < 4; i++) o[n][i] = 0.f;

    // ---- ldmatrix base addresses (bytes) ----
    const unsigned qAddr0 = su + 4u * (OFF_Q + (16 * w + l7 + 8 * l8) * QS2 + 4 * l16);
    const unsigned kOff = 4u * ((8 * l16 + l7) * KS2 + 4 * l8);
    const unsigned vOff = 4u * ((8 * l8 + l7) * VS2 + 4 * l16);

    for (int kt = 0; kt < ntiles; kt++) {
        const int s = kt % NSTAGE;
        const unsigned bufK = su + 4u * (OFF_B + s * BUFSZ);
        const unsigned bufV = bufK + 4u * (BN * KS2);

        // ---- prefetch tile kt+2 into stage (kt+2)%3 (read last at tile kt-1) ----
        if (kt + 2 < ntiles) {
            const int s2 = (kt + 2) % NSTAGE;
            unsigned nK = su + 4u * (OFF_B + s2 * BUFSZ);
            prefetch_tile(nK, nK + 4u * (BN * KS2),
                          kbase + (size_t)(kt + 2) * BN * 256,
                          vbase + (size_t)(kt + 2) * BN * 256, t);
        }

        // ---- S = Q @ K^T : single fp16 pass ----
        float sc[4][4];
        #pragma unroll
        for (int j = 0; j < 4; j++)
            #pragma unroll
            for (int i = 0; i < 4; i++) sc[j][i] = 0.f;

        const unsigned kAddr0 = bufK + kOff;
        #pragma unroll
        for (int kc = 0; kc < 8; kc++) {
            unsigned a0, a1, a2, a3;
            ldsm4(a0, a1, a2, a3, qAddr0 + kc * 32);
            unsigned b0[4], b1[4];
            ldsm4(b0[0], b0[1], b0[2], b0[3], kAddr0 + kc * 32);                 // n-tiles 0,1
            ldsm4(b1[0], b1[1], b1[2], b1[3], kAddr0 + 16 * KS2 * 4 + kc * 32);  // n-tiles 2,3
            mma_f16(sc[0], a0, a1, a2, a3, b0[0], b0[1]);
            mma_f16(sc[1], a0, a1, a2, a3, b0[2], b0[3]);
            mma_f16(sc[2], a0, a1, a2, a3, b1[0], b1[1]);
            mma_f16(sc[3], a0, a1, a2, a3, b1[2], b1[3]);
        }

        // ---- softmax numerator: p = 2^s, masked -> mk ----
        const int rel = vl - kt * BN;
        #pragma unroll
        for (int j = 0; j < 4; j++) {
            int c0 = 8 * j + 2 * q4;
            float p0 = ex2f(sc[j][0]);
            float p1 = ex2f(sc[j][1]);
            float p2 = ex2f(sc[j][2]);
            float p3 = ex2f(sc[j][3]);
            p0 = (c0     < rel) ? p0 : mk;
            p1 = (c0 + 1 < rel) ? p1 : mk;
            p2 = (c0     < rel) ? p2 : mk;
            p3 = (c0 + 1 < rel) ? p3 : mk;
            sc[j][0] = p0; sc[j][1] = p1; sc[j][2] = p2; sc[j][3] = p3;
            l_l += p0 + p1;
            l_h += p2 + p3;
        }

        // ---- O += P @ V : single fp16 pass, trans-ldmatrix B frags ----
        const unsigned vAddr0 = bufV + vOff;
        #pragma unroll
        for (int jj = 0; jj < 2; jj++) {
            unsigned a0 = f16pack(sc[2*jj][0],   sc[2*jj][1]);
            unsigned a1 = f16pack(sc[2*jj][2],   sc[2*jj][3]);
            unsigned a2 = f16pack(sc[2*jj+1][0], sc[2*jj+1][1]);
            unsigned a3 = f16pack(sc[2*jj+1][2], sc[2*jj+1][3]);
            unsigned vA = vAddr0 + jj * 16 * VS2 * 4;
            #pragma unroll
            for (int m = 0; m < 8; m++) {
                unsigned h0, h1, h2, h3;
                ldsm4t(h0, h1, h2, h3, vA + m * 32);
                mma_f16(o[2 * m],     a0, a1, a2, a3, h0, h1);
                mma_f16(o[2 * m + 1], a0, a1, a2, a3, h2, h3);
            }
        }

        // ---- rotate: ensure next tile's group landed; keep newest in flight ----
        if (kt + 1 < ntiles) {
            if (kt + 2 < ntiles) { CP_WAIT1(); } else { CP_WAIT0(); }
            __syncthreads();
        }
    }

    // ---- epilogue: reduce l over quad, normalize, store ----
    l_l += __shfl_xor_sync(0xffffffffu, l_l, 1);
    l_l += __shfl_xor_sync(0xffffffffu, l_l, 2);
    l_h += __shfl_xor_sync(0xffffffffu, l_h, 1);
    l_h += __shfl_xor_sync(0xffffffffu, l_h, 2);
    float inv_l = 1.0f / l_l;
    float inv_h = 1.0f / l_h;

    const int row_l = qb + 16 * w + g8;
    float* obase = Og + ((size_t)b * LSEQ) * DIM;
    #pragma unroll
    for (int n = 0; n < 16; n++) {
        int col = 8 * n + 2 * q4;
        float2 w0 = make_float2(o[n][0] * inv_l, o[n][1] * inv_l);
        float2 w1 = make_float2(o[n][2] * inv_h, o[n][3] * inv_h);
        *(float2*)&obase[(size_t)row_l * DIM + col] = w0;
        *(float2*)&obase[(size_t)(row_l + 8) * DIM + col] = w1;
    }
}

extern "C" void kernel_launch(void* const* d_in, const int* in_sizes, int n_in,
                              void* d_out, int out_size)
{
    const float* Q = (const float*)d_in[0];
    const float* K = (const float*)d_in[1];
    const float* V = (const float*)d_in[2];
    const void*  vlen = d_in[3];
    float* O = (float*)d_out;

    // pre-pass: convert only the K/V rows that will be read
    int n4 = BATCH * LSEQ * DIM / 4;
    cvt_kv_kernel<<<n4 / 256, 256>>>(K, V, vlen);

    cudaFuncSetAttribute(fa_f16_ring_kernel,
                         cudaFuncAttributeMaxDynamicSharedMemorySize, SMEM_BYTES);
    dim3 grid(LSEQ / BM, BATCH);
    fa_f16_ring_kernel<<<grid, NTH, SMEM_BYTES>>>(Q, vlen, O);
}